// round 15
// baseline (speedup 1.0000x reference)
#include <cuda_runtime.h>
#include <math.h>
#include <stdint.h>

// Problem shape (fixed)
#define BB 2
#define NN 8192
#define DD 256

// Scratch: tangent vectors, tf32-rounded.
__device__ float g_t [(size_t)BB * NN * DD];
__device__ float g_tT[(size_t)BB * DD * NN];

#define SW128(o) ((o) ^ ((((o) >> 3)) & 0x70))

// truncation-bias compensation for tf32-truncated adj operand (2^-11 * ln2)
#define CORR 1.000338f

// ===========================================================================
// Kernel 1: logmap0, round-to-nearest tf32.
// ===========================================================================
__global__ __launch_bounds__(256)
void tangent_kernel(const float* __restrict__ x) {
    __shared__ float sm[32 * 257];
    __shared__ float s_scale[32];

    const int blk = blockIdx.x;                // 0 .. 511
    const int b   = blk >> 8;
    const int n0  = (blk & 255) * 32;
    const int tid = threadIdx.x;

    const float* __restrict__ xb = x + ((size_t)b * NN + n0) * DD;

    #pragma unroll
    for (int i = 0; i < 32; i++) {
        int f = i * 256 + tid;
        int r = f >> 8, d = f & 255;
        sm[r * 257 + d] = xb[(size_t)r * DD + d];
    }
    __syncthreads();

    const int w = tid >> 5, l = tid & 31;
    #pragma unroll
    for (int q = 0; q < 4; q++) {
        int r = w * 4 + q;
        float s = 0.f;
        #pragma unroll
        for (int j = 0; j < 8; j++) {
            float v = sm[r * 257 + l + 32 * j];
            s = fmaf(v, v, s);
        }
        #pragma unroll
        for (int o = 16; o > 0; o >>= 1) s += __shfl_xor_sync(0xffffffffu, s, o);
        if (l == 0) {
            float n = sqrtf(s);
            float a = fminf(n, 1.0f - 1e-7f);
            s_scale[r] = atanhf(a) / fmaxf(n, 1e-15f);
        }
    }
    __syncthreads();

#if !(defined(__CUDA_ARCH__) && defined(__CUDA_ARCH_FEAT_SM103_ALL))
    float* __restrict__ tb = g_t + ((size_t)b * NN + n0) * DD;
    #pragma unroll
    for (int i = 0; i < 32; i++) {
        float v = sm[i * 257 + tid] * s_scale[i];
        uint32_t u;
        asm("cvt.rna.tf32.f32 %0, %1;" : "=r"(u) : "f"(v));
        tb[(size_t)i * DD + tid] = __uint_as_float(u);
    }
#endif

    float* __restrict__ tTb = g_tT + (size_t)b * DD * NN;
    #pragma unroll
    for (int i = 0; i < 32; i++) {
        int f = i * 256 + tid;
        int d = f >> 5, n_off = f & 31;
        float v = sm[n_off * 257 + d] * s_scale[n_off];
        uint32_t u;
        asm("cvt.rna.tf32.f32 %0, %1;" : "=r"(u) : "f"(v));
        tTb[(size_t)d * NN + n0 + n_off] = __uint_as_float(u);
    }
}

// ===========================================================================
// Shared helpers
// ===========================================================================
static __device__ __forceinline__ uint32_t smem_u32(const void* p) {
    uint32_t a;
    asm("{ .reg .u64 t; cvta.to.shared.u64 t, %1; cvt.u32.u64 %0, t; }"
        : "=r"(a) : "l"(p));
    return a;
}
static __device__ __forceinline__ void cp16(uint32_t dst, const void* src) {
    asm volatile("cp.async.cg.shared.global [%0], [%1], 16;"
                 :: "r"(dst), "l"(src) : "memory");
}

// ---- tcgen05 cg1: BK=32, split rings (A: 6 stages, B: 4 stages) ----
#define NKT    (NN / 32)         // 256
#define ASTAGES 6
#define BSTAGES 4
#define SOFF_A 1024
#define ASTG   16384             // 16 KB / A stage
#define SOFF_B (SOFF_A + ASTAGES * ASTG)      // 99328
#define BSTG   32768             // 32 KB / B stage
#define TC_SMEM (SOFF_B + BSTAGES * BSTG)     // 230400
#define EMPT_MB(i) (16 + 8 * (i))
#define FULL_MB(i) (48 + 8 * (i))
#define IDESC 0x08400910u
#define DESC_BASE ((2ULL << 61) | (1ULL << 46) | (64ULL << 32) | (1ULL << 16))

// ---- mma.sync fallback config (plain sm_103 path) ----
#define FB_ASTR 36
#define FB_BSTR 264
#define FB_ABYTES (128 * FB_ASTR * 4)
#define FB_BBYTES (32 * FB_BSTR * 4)
#define FB_STAGE  (FB_ABYTES + FB_BBYTES)
#define FB_SMEM   (3 * FB_STAGE)           // 156672

#define SMEM_DYN  (FB_SMEM > TC_SMEM ? FB_SMEM : TC_SMEM)

#if defined(__CUDA_ARCH__) && defined(__CUDA_ARCH_FEAT_SM103_ALL)
static __device__ __forceinline__ uint32_t elect_one() {
    uint32_t p;
    asm volatile("{\n\t.reg .pred p;\n\t"
                 "elect.sync _|p, 0xFFFFFFFF;\n\t"
                 "selp.b32 %0, 1, 0, p;\n\t}" : "=r"(p));
    return p;
}
static __device__ __forceinline__ void mbar_init(uint32_t mbar, uint32_t cnt) {
    asm volatile("mbarrier.init.shared.b64 [%0], %1;" :: "r"(mbar), "r"(cnt) : "memory");
}
static __device__ __forceinline__ void mbar_wait(uint32_t mbar, uint32_t parity) {
    asm volatile(
        "{\n\t.reg .pred P;\n\t"
        "W%=:\n\t"
        "mbarrier.try_wait.parity.acquire.cta.shared::cta.b64 P, [%0], %1, 0x989680;\n\t"
        "@P bra.uni D%=;\n\t"
        "bra.uni W%=;\n\t"
        "D%=:\n\t}"
        :: "r"(mbar), "r"(parity) : "memory");
}
static __device__ __forceinline__ void mbar_arrive_rel(uint32_t mbar) {
    asm volatile("mbarrier.arrive.release.cta.shared::cta.b64 _, [%0];"
                 :: "r"(mbar) : "memory");
}
static __device__ __forceinline__ void mma_tf32(uint32_t d_tmem, uint64_t a_desc,
                                                uint64_t b_desc, uint32_t en) {
    asm volatile(
        "{\n\t.reg .pred p;\n\t"
        "setp.ne.u32 p, %5, 0;\n\t"
        "tcgen05.mma.cta_group::1.kind::tf32 [%0], %1, %2, %3, {%4,%4,%4,%4}, p;\n\t}"
        :: "r"(d_tmem), "l"(a_desc), "l"(b_desc), "r"(IDESC), "r"(0u), "r"(en)
        : "memory");
}
static __device__ __forceinline__ void tmem_commit(uint32_t mbar) {
    asm volatile(
        "tcgen05.commit.cta_group::1.mbarrier::arrive::one.shared::cluster.b64 [%0];"
        :: "r"(mbar) : "memory");
}
static __device__ __forceinline__ uint64_t mk_desc(uint32_t addr) {
    return DESC_BASE | (uint64_t)((addr >> 4) & 0x3FFF);
}
#endif

// ===========================================================================
// Kernel 2: out = project(expmap0(adj @ t)), tcgen05 cg1.
// Split rings: A prefetch distance 4 (DRAM depth), B distance 2.
// ===========================================================================
__global__ __launch_bounds__(512, 1)
void hypagg_tc(const float* __restrict__ adj, float* __restrict__ out) {
#if defined(__CUDA_ARCH__) && defined(__CUDA_ARCH_FEAT_SM103_ALL)
    extern __shared__ char smem[];
    const uint32_t smb = smem_u32(smem);
    const int tid = threadIdx.x;
    const int wid = tid >> 5;
    const int lane = tid & 31;

    const int blk = blockIdx.x;          // 0..127
    const int b   = blk >> 6;
    const int i0  = (blk & 63) * 128;

    const float* __restrict__ adjB = adj + (size_t)b * NN * NN;
    const float* __restrict__ tTb  = g_tT + (size_t)b * DD * NN;

    // ---- producer chunk maps (threads 32..511 = 480 producers) ----
    // A: 1024 chunks (128 rows x 8): 64 threads x3 + 416 x2
    // B: 2048 chunks (256 rows x 8): 128 threads x5 + 352 x4
    const int p = tid - 32;
    const char* gqA[3]; uint32_t sbA[3]; int nA = 0;
    const char* gqB[5]; uint32_t sbB[5]; int nB = 0;
    if (tid >= 32) {
        nA = (p < 64) ? 3 : 2;
        #pragma unroll
        for (int j = 0; j < 3; j++) {
            int c = p + 480 * j;
            if (c < 1024) {
                int row = c >> 3, k4 = c & 7;
                gqA[j] = (const char*)(adjB + (size_t)(i0 + row) * NN) + k4 * 16;
                sbA[j] = SOFF_A + SW128(row * 128 + k4 * 16);
            }
        }
        nB = (p < 128) ? 5 : 4;
        #pragma unroll
        for (int j = 0; j < 5; j++) {
            int c = p + 480 * j;
            if (c < 2048) {
                int d = c >> 3, k4 = c & 7;
                gqB[j] = (const char*)(tTb + (size_t)d * NN) + k4 * 16;
                sbB[j] = SOFF_B + SW128(d * 128 + k4 * 16);
            }
        }
    }

    // ---- init: mbarriers + TMEM alloc ----
    if (tid == 0) {
        #pragma unroll
        for (int s = 0; s < 4; s++) {
            mbar_init(smb + EMPT_MB(s), 1);    // tcgen05.commit, ring 4
            mbar_init(smb + FULL_MB(s), 15);   // one arrive per producer warp
        }
    }
    if (wid == 0) {
        asm volatile("tcgen05.alloc.cta_group::1.sync.aligned.shared::cta.b32 [%0], %1;"
                     :: "r"(smb), "r"(256u) : "memory");
    }
    __syncthreads();
    uint32_t tmem;
    asm volatile("ld.shared.b32 %0, [%1];" : "=r"(tmem) : "r"(smb));

    const uint32_t is_we = elect_one();  // one leader lane per warp

    if (wid == 0) {
        // =============== MMA role: elected lane of warp 0, nothing else ====
        if (is_we) {
            int aslot = 0;
            for (int kt = 0; kt < NKT; kt++) {
                const int bslot = kt & 3;
                mbar_wait(smb + FULL_MB(bslot), (kt >> 2) & 1);
                asm volatile("fence.proxy.async.shared::cta;" ::: "memory");
                uint64_t ad = mk_desc(smb + SOFF_A + ((uint32_t)aslot << 14));
                uint64_t bd = mk_desc(smb + SOFF_B + ((uint32_t)bslot << 15));
                #pragma unroll
                for (int ks = 0; ks < 4; ks++)
                    mma_tf32(tmem, ad + 2 * ks, bd + 2 * ks,
                             (kt == 0 && ks == 0) ? 0u : 1u);
                tmem_commit(smb + EMPT_MB(bslot));
                aslot = (aslot == ASTAGES - 1) ? 0 : aslot + 1;
            }
        }
    } else {
        // =============== producer role: warps 1..15 ========================
        // prologue FIFO: GA0, GA1, GA2, GB0, GA3, GB1
        #pragma unroll
        for (int t = 0; t < 4; t++) {
            #pragma unroll
            for (int j = 0; j < 3; j++)
                if (j < nA)
                    cp16(smb + sbA[j] + (uint32_t)t * ASTG, gqA[j] + (size_t)t * 128);
            asm volatile("cp.async.commit_group;" ::: "memory");
            if (t >= 2) {
                const int tb = t - 2;
                #pragma unroll
                for (int j = 0; j < 5; j++)
                    if (j < nB)
                        cp16(smb + sbB[j] + (uint32_t)tb * BSTG, gqB[j] + (size_t)tb * 128);
                asm volatile("cp.async.commit_group;" ::: "memory");
            }
        }
        // advance running pointers: A to tile 4, B to tile 2
        #pragma unroll
        for (int j = 0; j < 3; j++) gqA[j] += 4 * 128;
        #pragma unroll
        for (int j = 0; j < 5; j++) gqB[j] += 2 * 128;

        int aslotP = 4;                  // slot for tile kt+4

        for (int kt = 0; kt < NKT; kt++) {
            // single gate for both rings: commit(kt-2)
            if (kt >= 2 && kt < NKT - 2)
                mbar_wait(smb + EMPT_MB((kt - 2) & 3), ((kt - 2) >> 2) & 1);

            if (kt < NKT - 4) {          // GA(kt+4) -> A slot aslotP
                const uint32_t aoff = (uint32_t)aslotP << 14;
                #pragma unroll
                for (int j = 0; j < 3; j++)
                    if (j < nA) cp16(smb + sbA[j] + aoff, gqA[j]);
                asm volatile("cp.async.commit_group;" ::: "memory");
                #pragma unroll
                for (int j = 0; j < 3; j++) gqA[j] += 128;
                aslotP = (aslotP == ASTAGES - 1) ? 0 : aslotP + 1;
            }
            if (kt < NKT - 2) {          // GB(kt+2) -> B slot (kt+2)&3
                const uint32_t boff = (uint32_t)((kt + 2) & 3) << 15;
                #pragma unroll
                for (int j = 0; j < 5; j++)
                    if (j < nB) cp16(smb + sbB[j] + boff, gqB[j]);
                asm volatile("cp.async.commit_group;" ::: "memory");
                #pragma unroll
                for (int j = 0; j < 5; j++) gqB[j] += 128;
            }

            // GA(kt) and GB(kt) complete when <= N newest groups pending
            if      (kt <  NKT - 4) asm volatile("cp.async.wait_group 4;" ::: "memory");
            else if (kt == NKT - 4) asm volatile("cp.async.wait_group 3;" ::: "memory");
            else if (kt == NKT - 3) asm volatile("cp.async.wait_group 2;" ::: "memory");
            else if (kt == NKT - 2) asm volatile("cp.async.wait_group 1;" ::: "memory");
            else                    asm volatile("cp.async.wait_group 0;" ::: "memory");

            __syncwarp();
            if (is_we) mbar_arrive_rel(smb + FULL_MB(kt & 3));
        }
    }

    // ---- all threads: wait for the final commit (tile NKT-1, slot 3) ----
    mbar_wait(smb + EMPT_MB((NKT - 1) & 3), ((NKT - 1) >> 2) & 1);
    asm volatile("tcgen05.fence::after_thread_sync;" ::: "memory");
    __syncthreads();

    // ---- epilogue: rows = wid*32+lane for warps 0-3 ----
    if (wid < 4) {
        const int grow = b * NN + i0 + wid * 32 + lane;
        float* __restrict__ op = out + (size_t)grow * DD;

        float ss = 0.f;
        #pragma unroll
        for (int c = 0; c < 8; c++) {
            uint32_t r[32];
            asm volatile(
                "tcgen05.ld.sync.aligned.32x32b.x32.b32 "
                "{%0,%1,%2,%3,%4,%5,%6,%7,%8,%9,%10,%11,%12,%13,%14,%15,"
                "%16,%17,%18,%19,%20,%21,%22,%23,%24,%25,%26,%27,%28,%29,%30,%31}, [%32];"
                : "=r"(r[0]),"=r"(r[1]),"=r"(r[2]),"=r"(r[3]),"=r"(r[4]),"=r"(r[5]),"=r"(r[6]),"=r"(r[7]),
                  "=r"(r[8]),"=r"(r[9]),"=r"(r[10]),"=r"(r[11]),"=r"(r[12]),"=r"(r[13]),"=r"(r[14]),"=r"(r[15]),
                  "=r"(r[16]),"=r"(r[17]),"=r"(r[18]),"=r"(r[19]),"=r"(r[20]),"=r"(r[21]),"=r"(r[22]),"=r"(r[23]),
                  "=r"(r[24]),"=r"(r[25]),"=r"(r[26]),"=r"(r[27]),"=r"(r[28]),"=r"(r[29]),"=r"(r[30]),"=r"(r[31])
                : "r"(tmem + c * 32));
            asm volatile("tcgen05.wait::ld.sync.aligned;" ::: "memory");
            #pragma unroll
            for (int i = 0; i < 32; i++) {
                float v = __uint_as_float(r[i]);
                ss = fmaf(v, v, ss);
            }
        }
        const float nr = fmaxf(sqrtf(ss), 1e-15f);
        const float n  = nr * CORR;
        const float th = tanhf(n);
        const float sc = (th > 1.0f - 4e-3f) ? ((1.0f - 4e-3f) / nr) : (th / nr);

        #pragma unroll
        for (int c = 0; c < 8; c++) {
            uint32_t r[32];
            asm volatile(
                "tcgen05.ld.sync.aligned.32x32b.x32.b32 "
                "{%0,%1,%2,%3,%4,%5,%6,%7,%8,%9,%10,%11,%12,%13,%14,%15,"
                "%16,%17,%18,%19,%20,%21,%22,%23,%24,%25,%26,%27,%28,%29,%30,%31}, [%32];"
                : "=r"(r[0]),"=r"(r[1]),"=r"(r[2]),"=r"(r[3]),"=r"(r[4]),"=r"(r[5]),"=r"(r[6]),"=r"(r[7]),
                  "=r"(r[8]),"=r"(r[9]),"=r"(r[10]),"=r"(r[11]),"=r"(r[12]),"=r"(r[13]),"=r"(r[14]),"=r"(r[15]),
                  "=r"(r[16]),"=r"(r[17]),"=r"(r[18]),"=r"(r[19]),"=r"(r[20]),"=r"(r[21]),"=r"(r[22]),"=r"(r[23]),
                  "=r"(r[24]),"=r"(r[25]),"=r"(r[26]),"=r"(r[27]),"=r"(r[28]),"=r"(r[29]),"=r"(r[30]),"=r"(r[31])
                : "r"(tmem + c * 32));
            asm volatile("tcgen05.wait::ld.sync.aligned;" ::: "memory");
            #pragma unroll
            for (int q = 0; q < 8; q++) {
                float4 v4;
                v4.x = __uint_as_float(r[q * 4 + 0]) * sc;
                v4.y = __uint_as_float(r[q * 4 + 1]) * sc;
                v4.z = __uint_as_float(r[q * 4 + 2]) * sc;
                v4.w = __uint_as_float(r[q * 4 + 3]) * sc;
                *(float4*)(op + c * 32 + q * 4) = v4;
            }
        }
    }

    __syncthreads();
    if (wid == 0) {
        asm volatile("tcgen05.dealloc.cta_group::1.sync.aligned.b32 %0, %1;"
                     :: "r"(tmem), "r"(256u));
    }

#elif defined(__CUDA_ARCH__)
    // =================== mma.sync tf32 fallback (plain sm_103) ===========
    extern __shared__ char smem[];
    const uint32_t smb = smem_u32(smem);
    const int tid  = threadIdx.x;
    const int wrp  = tid >> 5;
    const int lane = tid & 31;
    const int wm   = wrp & 1;
    const int wn   = wrp >> 1;
    const int g    = lane >> 2;
    const int tig  = lane & 3;

    const int blk = blockIdx.x;
    const int b   = blk >> 6;
    const int i0  = (blk & 63) * 128;

    const float* __restrict__ adjB = adj + (size_t)b * NN * NN;
    const float* __restrict__ tg   = g_t + (size_t)b * NN * DD;

    const char* gpA[2]; uint32_t soA[2];
    const char* gpB[4]; uint32_t soB[4];
    #pragma unroll
    for (int j = 0; j < 2; j++) {
        int c = tid + j * 512;
        int row = c >> 3, kc = c & 7;
        gpA[j] = (const char*)(adjB + (size_t)(i0 + row) * NN) + kc * 16;
        soA[j] = row * (FB_ASTR * 4) + kc * 16;
    }
    #pragma unroll
    for (int j = 0; j < 4; j++) {
        int c = tid + j * 512;
        int row = c >> 6, nc = c & 63;
        gpB[j] = (const char*)(tg + (size_t)row * DD) + nc * 16;
        soB[j] = FB_ABYTES + row * (FB_BSTR * 4) + nc * 16;
    }

    float cacc[4][4][4];
    #pragma unroll
    for (int i = 0; i < 4; i++)
        #pragma unroll
        for (int j = 0; j < 4; j++)
            #pragma unroll
            for (int q = 0; q < 4; q++) cacc[i][j][q] = 0.f;

    #pragma unroll
    for (int t0 = 0; t0 < 2; t0++) {
        #pragma unroll
        for (int j = 0; j < 2; j++)
            cp16(smb + t0 * FB_STAGE + soA[j], gpA[j] + (size_t)t0 * 128);
        #pragma unroll
        for (int j = 0; j < 4; j++)
            cp16(smb + t0 * FB_STAGE + soB[j], gpB[j] + (size_t)t0 * 32768);
        asm volatile("cp.async.commit_group;" ::: "memory");
    }

    const int NKTF = NN / 32;
    for (int kt = 0; kt < NKTF; kt++) {
        const int slot  = kt % 3;
        const int slotL = (kt + 2) % 3;
        if (kt + 2 < NKTF) {
            #pragma unroll
            for (int j = 0; j < 2; j++)
                cp16(smb + slotL * FB_STAGE + soA[j], gpA[j] + (size_t)(kt + 2) * 128);
            #pragma unroll
            for (int j = 0; j < 4; j++)
                cp16(smb + slotL * FB_STAGE + soB[j], gpB[j] + (size_t)(kt + 2) * 32768);
            asm volatile("cp.async.commit_group;" ::: "memory");
        }
        if      (kt <  NKTF - 2) asm volatile("cp.async.wait_group 2;" ::: "memory");
        else if (kt == NKTF - 2) asm volatile("cp.async.wait_group 1;" ::: "memory");
        else                     asm volatile("cp.async.wait_group 0;" ::: "memory");
        __syncthreads();

        const float* As = (const float*)(smem + slot * FB_STAGE);
        const float* Bs = (const float*)(smem + slot * FB_STAGE + FB_ABYTES);

        #pragma unroll
        for (int ks = 0; ks < 4; ks++) {
            const int kk = ks * 8;
            uint32_t a[4][4], bb[4][2];
            #pragma unroll
            for (int i = 0; i < 4; i++) {
                int r0 = wm * 64 + i * 16 + g;
                a[i][0] = __float_as_uint(As[(r0)     * FB_ASTR + kk + tig]);
                a[i][1] = __float_as_uint(As[(r0 + 8) * FB_ASTR + kk + tig]);
                a[i][2] = __float_as_uint(As[(r0)     * FB_ASTR + kk + tig + 4]);
                a[i][3] = __float_as_uint(As[(r0 + 8) * FB_ASTR + kk + tig + 4]);
            }
            #pragma unroll
            for (int j = 0; j < 4; j++) {
                int nn = wn * 32 + j * 8 + g;
                bb[j][0] = __float_as_uint(Bs[(kk + tig)     * FB_BSTR + nn]);
                bb[j][1] = __float_as_uint(Bs[(kk + tig + 4) * FB_BSTR + nn]);
            }
            #pragma unroll
            for (int i = 0; i < 4; i++)
                #pragma unroll
                for (int j = 0; j < 4; j++)
                    asm volatile(
                        "mma.sync.aligned.m16n8k8.row.col.f32.tf32.tf32.f32 "
                        "{%0,%1,%2,%3}, {%4,%5,%6,%7}, {%8,%9}, {%0,%1,%2,%3};"
                        : "+f"(cacc[i][j][0]), "+f"(cacc[i][j][1]),
                          "+f"(cacc[i][j][2]), "+f"(cacc[i][j][3])
                        : "r"(a[i][0]), "r"(a[i][1]), "r"(a[i][2]), "r"(a[i][3]),
                          "r"(bb[j][0]), "r"(bb[j][1]));
        }
        __syncthreads();
    }

    float* red = (float*)smem;
    float* scs = (float*)smem + 1024;

    #pragma unroll
    for (int i = 0; i < 4; i++) {
        int r0 = wm * 64 + i * 16 + g;
        float ss0 = 0.f, ss1 = 0.f;
        #pragma unroll
        for (int j = 0; j < 4; j++) {
            ss0 = fmaf(cacc[i][j][0], cacc[i][j][0], ss0);
            ss0 = fmaf(cacc[i][j][1], cacc[i][j][1], ss0);
            ss1 = fmaf(cacc[i][j][2], cacc[i][j][2], ss1);
            ss1 = fmaf(cacc[i][j][3], cacc[i][j][3], ss1);
        }
        ss0 += __shfl_xor_sync(0xffffffffu, ss0, 1);
        ss0 += __shfl_xor_sync(0xffffffffu, ss0, 2);
        ss1 += __shfl_xor_sync(0xffffffffu, ss1, 1);
        ss1 += __shfl_xor_sync(0xffffffffu, ss1, 2);
        if (tig == 0) {
            red[wn * 128 + r0]     = ss0;
            red[wn * 128 + r0 + 8] = ss1;
        }
    }
    __syncthreads();

    if (tid < 128) {
        float tot = 0.f;
        #pragma unroll
        for (int p2 = 0; p2 < 8; p2++) tot += red[p2 * 128 + tid];
        float nr = fmaxf(sqrtf(tot), 1e-15f);
        float n  = nr * CORR;
        float th = tanhf(n);
        scs[tid] = (th > 1.0f - 4e-3f) ? ((1.0f - 4e-3f) / nr) : (th / nr);
    }
    __syncthreads();

    #pragma unroll
    for (int i = 0; i < 4; i++) {
        int r0 = wm * 64 + i * 16 + g;
        float s0 = scs[r0], s1 = scs[r0 + 8];
        float* op0 = out + ((size_t)(b * NN + i0 + r0))     * DD + wn * 32 + 2 * tig;
        float* op1 = out + ((size_t)(b * NN + i0 + r0 + 8)) * DD + wn * 32 + 2 * tig;
        #pragma unroll
        for (int j = 0; j < 4; j++) {
            float2 v0 = make_float2(cacc[i][j][0] * s0, cacc[i][j][1] * s0);
            float2 v1 = make_float2(cacc[i][j][2] * s1, cacc[i][j][3] * s1);
            *(float2*)(op0 + j * 8) = v0;
            *(float2*)(op1 + j * 8) = v1;
        }
    }
#endif
}

// ===========================================================================
extern "C" void kernel_launch(void* const* d_in, const int* in_sizes, int n_in,
                              void* d_out, int out_size) {
    const float* x;
    const float* adj;
    if (in_sizes[0] < in_sizes[1]) { x = (const float*)d_in[0]; adj = (const float*)d_in[1]; }
    else                           { x = (const float*)d_in[1]; adj = (const float*)d_in[0]; }
    float* out = (float*)d_out;

    cudaFuncSetAttribute(hypagg_tc, cudaFuncAttributeMaxDynamicSharedMemorySize, SMEM_DYN);

    tangent_kernel<<<BB * NN / 32, 256>>>(x);
    hypagg_tc<<<128, 512, SMEM_DYN>>>(adj, out);
}

// round 16
// speedup vs baseline: 1.0205x; 1.0205x over previous
#include <cuda_runtime.h>
#include <math.h>
#include <stdint.h>

// Problem shape (fixed)
#define BB 2
#define NN 8192
#define DD 256

// Scratch: tangent vectors, tf32-rounded.
__device__ float g_t [(size_t)BB * NN * DD];
__device__ float g_tT[(size_t)BB * DD * NN];

#define SW128(o) ((o) ^ ((((o) >> 3)) & 0x70))

// truncation-bias compensation for tf32-truncated adj operand (2^-11 * ln2)
#define CORR 1.000338f

// ===========================================================================
// Kernel 1: logmap0, round-to-nearest tf32 (vectorized global I/O).
// ===========================================================================
__global__ __launch_bounds__(256)
void tangent_kernel(const float* __restrict__ x) {
    __shared__ float sm[32 * 257];
    __shared__ float s_scale[32];

    const int blk = blockIdx.x;                // 0 .. 511
    const int b   = blk >> 8;
    const int n0  = (blk & 255) * 32;
    const int tid = threadIdx.x;

    const float* __restrict__ xb = x + ((size_t)b * NN + n0) * DD;

    // load 32 rows x 256 dims as float4 (2048 LDG.128 per block)
    #pragma unroll
    for (int i = 0; i < 8; i++) {
        int f  = i * 256 + tid;        // float4 index: 0..2047
        int r  = f >> 6;               // 64 float4 per row
        int d4 = f & 63;
        float4 v = *(const float4*)(xb + (size_t)r * DD + d4 * 4);
        sm[r * 257 + d4 * 4 + 0] = v.x;
        sm[r * 257 + d4 * 4 + 1] = v.y;
        sm[r * 257 + d4 * 4 + 2] = v.z;
        sm[r * 257 + d4 * 4 + 3] = v.w;
    }
    __syncthreads();

    const int w = tid >> 5, l = tid & 31;
    #pragma unroll
    for (int q = 0; q < 4; q++) {
        int r = w * 4 + q;
        float s = 0.f;
        #pragma unroll
        for (int j = 0; j < 8; j++) {
            float v = sm[r * 257 + l + 32 * j];
            s = fmaf(v, v, s);
        }
        #pragma unroll
        for (int o = 16; o > 0; o >>= 1) s += __shfl_xor_sync(0xffffffffu, s, o);
        if (l == 0) {
            float n = sqrtf(s);
            float a = fminf(n, 1.0f - 1e-7f);
            s_scale[r] = atanhf(a) / fmaxf(n, 1e-15f);
        }
    }
    __syncthreads();

#if !(defined(__CUDA_ARCH__) && defined(__CUDA_ARCH_FEAT_SM103_ALL))
    // row-major write — only needed by the mma.sync fallback path
    float* __restrict__ tb = g_t + ((size_t)b * NN + n0) * DD;
    #pragma unroll
    for (int i = 0; i < 8; i++) {
        int f  = i * 256 + tid;
        int r  = f >> 6, d4 = f & 63;
        float sc = s_scale[r];
        float4 v;
        uint32_t u;
        asm("cvt.rna.tf32.f32 %0, %1;" : "=r"(u) : "f"(sm[r * 257 + d4 * 4 + 0] * sc)); v.x = __uint_as_float(u);
        asm("cvt.rna.tf32.f32 %0, %1;" : "=r"(u) : "f"(sm[r * 257 + d4 * 4 + 1] * sc)); v.y = __uint_as_float(u);
        asm("cvt.rna.tf32.f32 %0, %1;" : "=r"(u) : "f"(sm[r * 257 + d4 * 4 + 2] * sc)); v.z = __uint_as_float(u);
        asm("cvt.rna.tf32.f32 %0, %1;" : "=r"(u) : "f"(sm[r * 257 + d4 * 4 + 3] * sc)); v.w = __uint_as_float(u);
        *(float4*)(tb + (size_t)r * DD + d4 * 4) = v;
    }
#endif

    // transposed write: gather 4 n-values per thread, one STG.128
    // c = i*256+tid: d = c>>3 (0..255), n4 = c&7 (n = 4*n4 .. 4*n4+3)
    float* __restrict__ tTb = g_tT + (size_t)b * DD * NN;
    #pragma unroll
    for (int i = 0; i < 8; i++) {
        int c  = i * 256 + tid;
        int d  = c >> 3, n4 = c & 7;
        float4 v;
        uint32_t u;
        asm("cvt.rna.tf32.f32 %0, %1;" : "=r"(u) : "f"(sm[(n4 * 4 + 0) * 257 + d] * s_scale[n4 * 4 + 0])); v.x = __uint_as_float(u);
        asm("cvt.rna.tf32.f32 %0, %1;" : "=r"(u) : "f"(sm[(n4 * 4 + 1) * 257 + d] * s_scale[n4 * 4 + 1])); v.y = __uint_as_float(u);
        asm("cvt.rna.tf32.f32 %0, %1;" : "=r"(u) : "f"(sm[(n4 * 4 + 2) * 257 + d] * s_scale[n4 * 4 + 2])); v.z = __uint_as_float(u);
        asm("cvt.rna.tf32.f32 %0, %1;" : "=r"(u) : "f"(sm[(n4 * 4 + 3) * 257 + d] * s_scale[n4 * 4 + 3])); v.w = __uint_as_float(u);
        *(float4*)(tTb + (size_t)d * NN + n0 + n4 * 4) = v;
    }
}

// ===========================================================================
// Shared helpers
// ===========================================================================
static __device__ __forceinline__ uint32_t smem_u32(const void* p) {
    uint32_t a;
    asm("{ .reg .u64 t; cvta.to.shared.u64 t, %1; cvt.u32.u64 %0, t; }"
        : "=r"(a) : "l"(p));
    return a;
}
static __device__ __forceinline__ void cp16(uint32_t dst, const void* src) {
    asm volatile("cp.async.cg.shared.global [%0], [%1], 16;"
                 :: "r"(dst), "l"(src) : "memory");
}

// ---- tcgen05 cg1: BK=32, 4-stage ring, dedicated MMA warp ----
#define NKT    (NN / 32)         // 256
#define STAGES 4
#define SOFF_A 1024
#define ASTG   (128 * 128)       // 16 KB / stage
#define SOFF_B (SOFF_A + STAGES * ASTG)
#define BSTG   (256 * 128)       // 32 KB / stage
#define TC_SMEM (SOFF_B + STAGES * BSTG)      // 197632
#define EMPT_MB(i) (16 + 8 * (i))
#define FULL_MB(i) (48 + 8 * (i))
#define IDESC 0x08400910u
#define DESC_BASE ((2ULL << 61) | (1ULL << 46) | (64ULL << 32) | (1ULL << 16))

// ---- mma.sync fallback config (plain sm_103 path) ----
#define FB_ASTR 36
#define FB_BSTR 264
#define FB_ABYTES (128 * FB_ASTR * 4)
#define FB_BBYTES (32 * FB_BSTR * 4)
#define FB_STAGE  (FB_ABYTES + FB_BBYTES)
#define FB_SMEM   (3 * FB_STAGE)           // 156672

#define SMEM_DYN  (FB_SMEM > TC_SMEM ? FB_SMEM : TC_SMEM)

#if defined(__CUDA_ARCH__) && defined(__CUDA_ARCH_FEAT_SM103_ALL)
static __device__ __forceinline__ uint32_t elect_one() {
    uint32_t p;
    asm volatile("{\n\t.reg .pred p;\n\t"
                 "elect.sync _|p, 0xFFFFFFFF;\n\t"
                 "selp.b32 %0, 1, 0, p;\n\t}" : "=r"(p));
    return p;
}
static __device__ __forceinline__ void mbar_init(uint32_t mbar, uint32_t cnt) {
    asm volatile("mbarrier.init.shared.b64 [%0], %1;" :: "r"(mbar), "r"(cnt) : "memory");
}
static __device__ __forceinline__ void mbar_wait(uint32_t mbar, uint32_t parity) {
    asm volatile(
        "{\n\t.reg .pred P;\n\t"
        "W%=:\n\t"
        "mbarrier.try_wait.parity.acquire.cta.shared::cta.b64 P, [%0], %1, 0x989680;\n\t"
        "@P bra.uni D%=;\n\t"
        "bra.uni W%=;\n\t"
        "D%=:\n\t}"
        :: "r"(mbar), "r"(parity) : "memory");
}
static __device__ __forceinline__ void mbar_arrive_rel(uint32_t mbar) {
    asm volatile("mbarrier.arrive.release.cta.shared::cta.b64 _, [%0];"
                 :: "r"(mbar) : "memory");
}
static __device__ __forceinline__ void mma_tf32(uint32_t d_tmem, uint64_t a_desc,
                                                uint64_t b_desc, uint32_t en) {
    asm volatile(
        "{\n\t.reg .pred p;\n\t"
        "setp.ne.u32 p, %5, 0;\n\t"
        "tcgen05.mma.cta_group::1.kind::tf32 [%0], %1, %2, %3, {%4,%4,%4,%4}, p;\n\t}"
        :: "r"(d_tmem), "l"(a_desc), "l"(b_desc), "r"(IDESC), "r"(0u), "r"(en)
        : "memory");
}
static __device__ __forceinline__ void tmem_commit(uint32_t mbar) {
    asm volatile(
        "tcgen05.commit.cta_group::1.mbarrier::arrive::one.shared::cluster.b64 [%0];"
        :: "r"(mbar) : "memory");
}
static __device__ __forceinline__ uint64_t mk_desc(uint32_t addr) {
    return DESC_BASE | (uint64_t)((addr >> 4) & 0x3FFF);
}
#endif

// ===========================================================================
// Kernel 2: out = project(expmap0(adj @ t)), tcgen05 cg1.
// R14 champion: 4x-unrolled producer loop, register-resident addresses.
// ===========================================================================
__global__ __launch_bounds__(512, 1)
void hypagg_tc(const float* __restrict__ adj, float* __restrict__ out) {
#if defined(__CUDA_ARCH__) && defined(__CUDA_ARCH_FEAT_SM103_ALL)
    extern __shared__ char smem[];
    const uint32_t smb = smem_u32(smem);
    const int tid = threadIdx.x;
    const int wid = tid >> 5;
    const int lane = tid & 31;

    const int blk = blockIdx.x;          // 0..127
    const int b   = blk >> 6;
    const int i0  = (blk & 63) * 128;

    const float* __restrict__ adjB = adj + (size_t)b * NN * NN;
    const float* __restrict__ tTb  = g_tT + (size_t)b * DD * NN;

    // ---- producer chunk map: threads 32..511 (480 threads), 3072 chunks ----
    const int p = tid - 32;
    const char* gp[7];
    uint32_t sb_off[7], sstep[7];
    int nch = 0;
    if (tid >= 32) {
        nch = (p < 192) ? 7 : 6;         // 192*7 + 288*6 = 3072
        #pragma unroll
        for (int j = 0; j < 7; j++) {
            int c = p + 480 * j;
            if (c >= 3072) break;
            if (c < 1024) {              // A: 128 rows x 8 chunks
                int row = c >> 3, k4 = c & 7;
                gp[j] = (const char*)(adjB + (size_t)(i0 + row) * NN) + k4 * 16;
                sb_off[j] = SOFF_A + SW128(row * 128 + k4 * 16);
                sstep[j]  = ASTG;
            } else {                     // B: 256 rows x 8 chunks
                int cc = c - 1024;
                int d = cc >> 3, k4 = cc & 7;
                gp[j] = (const char*)(tTb + (size_t)d * NN) + k4 * 16;
                sb_off[j] = SOFF_B + SW128(d * 128 + k4 * 16);
                sstep[j]  = BSTG;
            }
        }
    }

    // ---- init: mbarriers + TMEM alloc ----
    if (tid == 0) {
        #pragma unroll
        for (int s = 0; s < STAGES; s++) {
            mbar_init(smb + EMPT_MB(s), 1);    // tcgen05.commit
            mbar_init(smb + FULL_MB(s), 15);   // one arrive per producer warp
        }
    }
    if (wid == 0) {
        asm volatile("tcgen05.alloc.cta_group::1.sync.aligned.shared::cta.b32 [%0], %1;"
                     :: "r"(smb), "r"(256u) : "memory");
    }
    __syncthreads();
    uint32_t tmem;
    asm volatile("ld.shared.b32 %0, [%1];" : "=r"(tmem) : "r"(smb));

    const uint32_t is_we = elect_one();  // one leader lane per warp

    if (wid == 0) {
        // =============== MMA role: elected lane of warp 0, nothing else ====
        if (is_we) {
            for (int kt = 0; kt < NKT; kt++) {
                const int slot = kt & 3;
                mbar_wait(smb + FULL_MB(slot), (kt >> 2) & 1);
                asm volatile("fence.proxy.async.shared::cta;" ::: "memory");
                uint64_t ad = mk_desc(smb + SOFF_A + slot * ASTG);
                uint64_t bd = mk_desc(smb + SOFF_B + slot * BSTG);
                #pragma unroll
                for (int ks = 0; ks < 4; ks++)
                    mma_tf32(tmem, ad + 2 * ks, bd + 2 * ks,
                             (kt == 0 && ks == 0) ? 0u : 1u);
                tmem_commit(smb + EMPT_MB(slot));
            }
        }
    } else {
        // =============== producer role: warps 1..15 ========================
        // register-resident smem addresses for all 4 slots x 7 chunks
        uint32_t sadr[4][7];
        #pragma unroll
        for (int s = 0; s < 4; s++)
            #pragma unroll
            for (int j = 0; j < 7; j++)
                sadr[s][j] = smb + sb_off[j] + (uint32_t)s * sstep[j];

        // prologue: tiles 0,1 into slots 0,1
        #pragma unroll
        for (int t0 = 0; t0 < 2; t0++) {
            #pragma unroll
            for (int j = 0; j < 7; j++)
                if (j < nch)
                    cp16(sadr[t0][j], gp[j] + (size_t)t0 * 128);
            asm volatile("cp.async.commit_group;" ::: "memory");
        }

        // running global pointers, starting at tile 2
        const char* gq[7];
        #pragma unroll
        for (int j = 0; j < 7; j++) gq[j] = gp[j] + 2 * 128;

        // main loop, manually 4x-unrolled so slot indices are compile-time
        for (int kb = 0; kb < NKT; kb += 4) {
            #pragma unroll
            for (int u = 0; u < 4; u++) {
                const int kt = kb + u;
                const int slotL = (u + 2) & 3;   // compile-time
                if (kt <= NKT - 3) {
                    if (kt >= 2)
                        mbar_wait(smb + EMPT_MB(slotL), ((kt - 2) >> 2) & 1);
                    #pragma unroll
                    for (int j = 0; j < 7; j++)
                        if (j < nch)
                            cp16(sadr[slotL][j], gq[j]);
                    asm volatile("cp.async.commit_group;" ::: "memory");
                }
                #pragma unroll
                for (int j = 0; j < 7; j++) gq[j] += 128;
                if      (kt <  NKT - 2) asm volatile("cp.async.wait_group 2;" ::: "memory");
                else if (kt == NKT - 2) asm volatile("cp.async.wait_group 1;" ::: "memory");
                else                    asm volatile("cp.async.wait_group 0;" ::: "memory");

                // per-warp readiness signal for tile kt (slot = u)
                __syncwarp();
                if (is_we) mbar_arrive_rel(smb + FULL_MB(u));
            }
        }
    }

    // ---- all threads: wait for the final commit (tile NKT-1, slot 3) ----
    mbar_wait(smb + EMPT_MB((NKT - 1) & 3), ((NKT - 1) >> 2) & 1);
    asm volatile("tcgen05.fence::after_thread_sync;" ::: "memory");
    __syncthreads();

    // ---- epilogue: rows = wid*32+lane for warps 0-3 ----
    if (wid < 4) {
        const int grow = b * NN + i0 + wid * 32 + lane;
        float* __restrict__ op = out + (size_t)grow * DD;

        float ss = 0.f;
        #pragma unroll
        for (int c = 0; c < 8; c++) {
            uint32_t r[32];
            asm volatile(
                "tcgen05.ld.sync.aligned.32x32b.x32.b32 "
                "{%0,%1,%2,%3,%4,%5,%6,%7,%8,%9,%10,%11,%12,%13,%14,%15,"
                "%16,%17,%18,%19,%20,%21,%22,%23,%24,%25,%26,%27,%28,%29,%30,%31}, [%32];"
                : "=r"(r[0]),"=r"(r[1]),"=r"(r[2]),"=r"(r[3]),"=r"(r[4]),"=r"(r[5]),"=r"(r[6]),"=r"(r[7]),
                  "=r"(r[8]),"=r"(r[9]),"=r"(r[10]),"=r"(r[11]),"=r"(r[12]),"=r"(r[13]),"=r"(r[14]),"=r"(r[15]),
                  "=r"(r[16]),"=r"(r[17]),"=r"(r[18]),"=r"(r[19]),"=r"(r[20]),"=r"(r[21]),"=r"(r[22]),"=r"(r[23]),
                  "=r"(r[24]),"=r"(r[25]),"=r"(r[26]),"=r"(r[27]),"=r"(r[28]),"=r"(r[29]),"=r"(r[30]),"=r"(r[31])
                : "r"(tmem + c * 32));
            asm volatile("tcgen05.wait::ld.sync.aligned;" ::: "memory");
            #pragma unroll
            for (int i = 0; i < 32; i++) {
                float v = __uint_as_float(r[i]);
                ss = fmaf(v, v, ss);
            }
        }
        const float nr = fmaxf(sqrtf(ss), 1e-15f);
        const float n  = nr * CORR;
        const float th = tanhf(n);
        const float sc = (th > 1.0f - 4e-3f) ? ((1.0f - 4e-3f) / nr) : (th / nr);

        #pragma unroll
        for (int c = 0; c < 8; c++) {
            uint32_t r[32];
            asm volatile(
                "tcgen05.ld.sync.aligned.32x32b.x32.b32 "
                "{%0,%1,%2,%3,%4,%5,%6,%7,%8,%9,%10,%11,%12,%13,%14,%15,"
                "%16,%17,%18,%19,%20,%21,%22,%23,%24,%25,%26,%27,%28,%29,%30,%31}, [%32];"
                : "=r"(r[0]),"=r"(r[1]),"=r"(r[2]),"=r"(r[3]),"=r"(r[4]),"=r"(r[5]),"=r"(r[6]),"=r"(r[7]),
                  "=r"(r[8]),"=r"(r[9]),"=r"(r[10]),"=r"(r[11]),"=r"(r[12]),"=r"(r[13]),"=r"(r[14]),"=r"(r[15]),
                  "=r"(r[16]),"=r"(r[17]),"=r"(r[18]),"=r"(r[19]),"=r"(r[20]),"=r"(r[21]),"=r"(r[22]),"=r"(r[23]),
                  "=r"(r[24]),"=r"(r[25]),"=r"(r[26]),"=r"(r[27]),"=r"(r[28]),"=r"(r[29]),"=r"(r[30]),"=r"(r[31])
                : "r"(tmem + c * 32));
            asm volatile("tcgen05.wait::ld.sync.aligned;" ::: "memory");
            #pragma unroll
            for (int q = 0; q < 8; q++) {
                float4 v4;
                v4.x = __uint_as_float(r[q * 4 + 0]) * sc;
                v4.y = __uint_as_float(r[q * 4 + 1]) * sc;
                v4.z = __uint_as_float(r[q * 4 + 2]) * sc;
                v4.w = __uint_as_float(r[q * 4 + 3]) * sc;
                *(float4*)(op + c * 32 + q * 4) = v4;
            }
        }
    }

    __syncthreads();
    if (wid == 0) {
        asm volatile("tcgen05.dealloc.cta_group::1.sync.aligned.b32 %0, %1;"
                     :: "r"(tmem), "r"(256u));
    }

#elif defined(__CUDA_ARCH__)
    // =================== mma.sync tf32 fallback (plain sm_103) ===========
    extern __shared__ char smem[];
    const uint32_t smb = smem_u32(smem);
    const int tid  = threadIdx.x;
    const int wrp  = tid >> 5;
    const int lane = tid & 31;
    const int wm   = wrp & 1;
    const int wn   = wrp >> 1;
    const int g    = lane >> 2;
    const int tig  = lane & 3;

    const int blk = blockIdx.x;
    const int b   = blk >> 6;
    const int i0  = (blk & 63) * 128;

    const float* __restrict__ adjB = adj + (size_t)b * NN * NN;
    const float* __restrict__ tg   = g_t + (size_t)b * NN * DD;

    const char* gpA[2]; uint32_t soA[2];
    const char* gpB[4]; uint32_t soB[4];
    #pragma unroll
    for (int j = 0; j < 2; j++) {
        int c = tid + j * 512;
        int row = c >> 3, kc = c & 7;
        gpA[j] = (const char*)(adjB + (size_t)(i0 + row) * NN) + kc * 16;
        soA[j] = row * (FB_ASTR * 4) + kc * 16;
    }
    #pragma unroll
    for (int j = 0; j < 4; j++) {
        int c = tid + j * 512;
        int row = c >> 6, nc = c & 63;
        gpB[j] = (const char*)(tg + (size_t)row * DD) + nc * 16;
        soB[j] = FB_ABYTES + row * (FB_BSTR * 4) + nc * 16;
    }

    float cacc[4][4][4];
    #pragma unroll
    for (int i = 0; i < 4; i++)
        #pragma unroll
        for (int j = 0; j < 4; j++)
            #pragma unroll
            for (int q = 0; q < 4; q++) cacc[i][j][q] = 0.f;

    #pragma unroll
    for (int t0 = 0; t0 < 2; t0++) {
        #pragma unroll
        for (int j = 0; j < 2; j++)
            cp16(smb + t0 * FB_STAGE + soA[j], gpA[j] + (size_t)t0 * 128);
        #pragma unroll
        for (int j = 0; j < 4; j++)
            cp16(smb + t0 * FB_STAGE + soB[j], gpB[j] + (size_t)t0 * 32768);
        asm volatile("cp.async.commit_group;" ::: "memory");
    }

    const int NKTF = NN / 32;
    for (int kt = 0; kt < NKTF; kt++) {
        const int slot  = kt % 3;
        const int slotL = (kt + 2) % 3;
        if (kt + 2 < NKTF) {
            #pragma unroll
            for (int j = 0; j < 2; j++)
                cp16(smb + slotL * FB_STAGE + soA[j], gpA[j] + (size_t)(kt + 2) * 128);
            #pragma unroll
            for (int j = 0; j < 4; j++)
                cp16(smb + slotL * FB_STAGE + soB[j], gpB[j] + (size_t)(kt + 2) * 32768);
            asm volatile("cp.async.commit_group;" ::: "memory");
        }
        if      (kt <  NKTF - 2) asm volatile("cp.async.wait_group 2;" ::: "memory");
        else if (kt == NKTF - 2) asm volatile("cp.async.wait_group 1;" ::: "memory");
        else                     asm volatile("cp.async.wait_group 0;" ::: "memory");
        __syncthreads();

        const float* As = (const float*)(smem + slot * FB_STAGE);
        const float* Bs = (const float*)(smem + slot * FB_STAGE + FB_ABYTES);

        #pragma unroll
        for (int ks = 0; ks < 4; ks++) {
            const int kk = ks * 8;
            uint32_t a[4][4], bb[4][2];
            #pragma unroll
            for (int i = 0; i < 4; i++) {
                int r0 = wm * 64 + i * 16 + g;
                a[i][0] = __float_as_uint(As[(r0)     * FB_ASTR + kk + tig]);
                a[i][1] = __float_as_uint(As[(r0 + 8) * FB_ASTR + kk + tig]);
                a[i][2] = __float_as_uint(As[(r0)     * FB_ASTR + kk + tig + 4]);
                a[i][3] = __float_as_uint(As[(r0 + 8) * FB_ASTR + kk + tig + 4]);
            }
            #pragma unroll
            for (int j = 0; j < 4; j++) {
                int nn = wn * 32 + j * 8 + g;
                bb[j][0] = __float_as_uint(Bs[(kk + tig)     * FB_BSTR + nn]);
                bb[j][1] = __float_as_uint(Bs[(kk + tig + 4) * FB_BSTR + nn]);
            }
            #pragma unroll
            for (int i = 0; i < 4; i++)
                #pragma unroll
                for (int j = 0; j < 4; j++)
                    asm volatile(
                        "mma.sync.aligned.m16n8k8.row.col.f32.tf32.tf32.f32 "
                        "{%0,%1,%2,%3}, {%4,%5,%6,%7}, {%8,%9}, {%0,%1,%2,%3};"
                        : "+f"(cacc[i][j][0]), "+f"(cacc[i][j][1]),
                          "+f"(cacc[i][j][2]), "+f"(cacc[i][j][3])
                        : "r"(a[i][0]), "r"(a[i][1]), "r"(a[i][2]), "r"(a[i][3]),
                          "r"(bb[j][0]), "r"(bb[j][1]));
        }
        __syncthreads();
    }

    float* red = (float*)smem;
    float* scs = (float*)smem + 1024;

    #pragma unroll
    for (int i = 0; i < 4; i++) {
        int r0 = wm * 64 + i * 16 + g;
        float ss0 = 0.f, ss1 = 0.f;
        #pragma unroll
        for (int j = 0; j < 4; j++) {
            ss0 = fmaf(cacc[i][j][0], cacc[i][j][0], ss0);
            ss0 = fmaf(cacc[i][j][1], cacc[i][j][1], ss0);
            ss1 = fmaf(cacc[i][j][2], cacc[i][j][2], ss1);
            ss1 = fmaf(cacc[i][j][3], cacc[i][j][3], ss1);
        }
        ss0 += __shfl_xor_sync(0xffffffffu, ss0, 1);
        ss0 += __shfl_xor_sync(0xffffffffu, ss0, 2);
        ss1 += __shfl_xor_sync(0xffffffffu, ss1, 1);
        ss1 += __shfl_xor_sync(0xffffffffu, ss1, 2);
        if (tig == 0) {
            red[wn * 128 + r0]     = ss0;
            red[wn * 128 + r0 + 8] = ss1;
        }
    }
    __syncthreads();

    if (tid < 128) {
        float tot = 0.f;
        #pragma unroll
        for (int p2 = 0; p2 < 8; p2++) tot += red[p2 * 128 + tid];
        float nr = fmaxf(sqrtf(tot), 1e-15f);
        float n  = nr * CORR;
        float th = tanhf(n);
        scs[tid] = (th > 1.0f - 4e-3f) ? ((1.0f - 4e-3f) / nr) : (th / nr);
    }
    __syncthreads();

    #pragma unroll
    for (int i = 0; i < 4; i++) {
        int r0 = wm * 64 + i * 16 + g;
        float s0 = scs[r0], s1 = scs[r0 + 8];
        float* op0 = out + ((size_t)(b * NN + i0 + r0))     * DD + wn * 32 + 2 * tig;
        float* op1 = out + ((size_t)(b * NN + i0 + r0 + 8)) * DD + wn * 32 + 2 * tig;
        #pragma unroll
        for (int j = 0; j < 4; j++) {
            float2 v0 = make_float2(cacc[i][j][0] * s0, cacc[i][j][1] * s0);
            float2 v1 = make_float2(cacc[i][j][2] * s1, cacc[i][j][3] * s1);
            *(float2*)(op0 + j * 8) = v0;
            *(float2*)(op1 + j * 8) = v1;
        }
    }
#endif
}

// ===========================================================================
extern "C" void kernel_launch(void* const* d_in, const int* in_sizes, int n_in,
                              void* d_out, int out_size) {
    const float* x;
    const float* adj;
    if (in_sizes[0] < in_sizes[1]) { x = (const float*)d_in[0]; adj = (const float*)d_in[1]; }
    else                           { x = (const float*)d_in[1]; adj = (const float*)d_in[0]; }
    float* out = (float*)d_out;

    cudaFuncSetAttribute(hypagg_tc, cudaFuncAttributeMaxDynamicSharedMemorySize, SMEM_DYN);

    tangent_kernel<<<BB * NN / 32, 256>>>(x);
    hypagg_tc<<<128, 512, SMEM_DYN>>>(adj, out);
}